// round 1
// baseline (speedup 1.0000x reference)
#include <cuda_runtime.h>
#include <cstddef>

// Problem shapes (fixed for SNNLayer_57930518888891):
//   x: (B=16, C=1024, T=2048) fp32
//   weight: (N=1024, C=1024) fp32, indexed [o, n] by the einsum
//   v0: (N=1024,) fp32
//   out: (B, N, T) fp32 spikes
//
// Math: einsum('bct,on->bnt') factorizes: inp[b,n,t] = sx[b,t] * cs[n]
// where sx[b,t] = sum_c x[b,c,t], cs[n] = sum_o w[o,n].

#define BB 16
#define CC 1024
#define TT 2048
#define NN 1024
#define OCHUNKS 16
#define OPER    (CC / OCHUNKS)   // 64 rows per chunk

__device__ float g_sx[BB * TT];             // 128 KB
__device__ float g_cs[NN];                  // 4 KB
__device__ float g_cs_part[OCHUNKS * NN];   // 64 KB

// ---------------------------------------------------------------------------
// Kernel 1a: partial column sums of weight.  grid (NN/256, OCHUNKS), block 256
// Each thread sums OPER consecutive rows (sequential order within chunk).
// ---------------------------------------------------------------------------
__global__ void colsum_part_kernel(const float* __restrict__ w) {
    const int n  = blockIdx.x * 256 + threadIdx.x;
    const int oc = blockIdx.y;
    const float* p = w + (size_t)oc * OPER * NN + n;
    float acc = 0.0f;
#pragma unroll 16
    for (int o = 0; o < OPER; ++o) {
        acc = __fadd_rn(acc, p[(size_t)o * NN]);
    }
    g_cs_part[oc * NN + n] = acc;
}

// ---------------------------------------------------------------------------
// Kernel 1b: reduce partials (sequential in chunk order).  grid 4, block 256
// ---------------------------------------------------------------------------
__global__ void colsum_reduce_kernel() {
    const int n = blockIdx.x * 256 + threadIdx.x;
    float acc = 0.0f;
#pragma unroll
    for (int oc = 0; oc < OCHUNKS; ++oc) {
        acc = __fadd_rn(acc, g_cs_part[oc * NN + n]);
    }
    g_cs[n] = acc;
}

// ---------------------------------------------------------------------------
// Kernel 2: sx[b,t] = sum_c x[b,c,t].  One thread per (b,t).
// grid BB*TT/256 = 128 blocks, block 256. Coalesced 128B warp loads.
// Single accumulator keeps sequential-in-c order (precision fidelity);
// unroll lets ptxas batch independent loads (MLP ~16).
// ---------------------------------------------------------------------------
__global__ void rowsum_kernel(const float* __restrict__ x) {
    const int idx = blockIdx.x * 256 + threadIdx.x;   // b*TT + t
    const int b = idx / TT;
    const int t = idx % TT;
    const float* p = x + (size_t)b * CC * TT + t;
    float acc = 0.0f;
#pragma unroll 16
    for (int c = 0; c < CC; ++c) {
        acc = __fadd_rn(acc, p[(size_t)c * TT]);
    }
    g_sx[idx] = acc;
}

// ---------------------------------------------------------------------------
// Kernel 3: LIF recurrence + coalesced spike writes.
// grid (NN/64, BB) = 256 blocks, block 64 (each thread owns one n).
// Per 32-timestep chunk: compute spikes into SMEM with rotate swizzle
// buf[k][(tid+k)&63] (conflict-free STS and transposed LDS), then the two
// warps write 128B-coalesced rows of out.
// Arithmetic matches reference order exactly: v += (i - v) * 0.1 (no FMA).
// ---------------------------------------------------------------------------
#define TC 32

__global__ void lif_kernel(const float* __restrict__ v0,
                           float* __restrict__ out) {
    const int tid = threadIdx.x;              // 0..63
    const int n0  = blockIdx.x * 64;
    const int b   = blockIdx.y;
    const int n   = n0 + tid;

    __shared__ float sxs[TC];
    __shared__ float buf[TC * 64];

    const float csn = g_cs[n];
    float v = v0[n];

    float* outb = out + ((size_t)b * NN + n0) * TT;
    const float* sxb = g_sx + b * TT;

    const int w    = tid >> 5;
    const int lane = tid & 31;

    for (int t0 = 0; t0 < TT; t0 += TC) {
        if (tid < TC) sxs[tid] = sxb[t0 + tid];
        __syncthreads();

#pragma unroll
        for (int k = 0; k < TC; ++k) {
            float cur = __fmul_rn(sxs[k], csn);
            float dv  = __fmul_rn(__fsub_rn(cur, v), 0.1f);
            v = __fadd_rn(v, dv);
            float s;
            if (v >= 1.0f) { s = 1.0f; v = 0.0f; } else { s = 0.0f; }
            buf[k * 64 + ((tid + k) & 63)] = s;
        }
        __syncthreads();

        // Transposed, coalesced write-out: warp w handles rows r = w, w+2, ...
        for (int r = w; r < 64; r += 2) {
            float val = buf[lane * 64 + ((r + lane) & 63)];
            outb[(size_t)r * TT + t0 + lane] = val;
        }
        __syncthreads();
    }
}

// ---------------------------------------------------------------------------
extern "C" void kernel_launch(void* const* d_in, const int* in_sizes, int n_in,
                              void* d_out, int out_size) {
    const float* x  = (const float*)d_in[0];
    const float* wt = (const float*)d_in[1];
    const float* v0 = (const float*)d_in[2];
    float* out = (float*)d_out;

    (void)in_sizes; (void)n_in; (void)out_size;

    colsum_part_kernel<<<dim3(NN / 256, OCHUNKS), 256>>>(wt);
    colsum_reduce_kernel<<<NN / 256, 256>>>();
    rowsum_kernel<<<(BB * TT) / 256, 256>>>(x);
    lif_kernel<<<dim3(NN / 64, BB), 64>>>(v0, out);
}

// round 2
// speedup vs baseline: 2.0317x; 2.0317x over previous
#include <cuda_runtime.h>
#include <cstddef>

// SNNLayer: x(16,1024,2048) fp32, weight(1024,1024) fp32, v0(1024) fp32
// einsum('bct,on->bnt') factorizes: inp[b,n,t] = sx[b,t] * cs[n]
//   sx[b,t] = sum_c x[b,c,t]   (sequential-c order, kept EXACTLY as round 1)
//   cs[n]   = sum_o w[o,n]     (16 chunks of 64, sequential, as round 1)
// LIF: v += (i - v)*0.1 ; spike = v>=1 ; reset to exact 0.
//
// Parallel-in-T: 8 segments x 256 steps, each (except s=0) warmed up from
// v=0 over 128 steps. Hard reset -> exact resync; residual decays 0.9^128.

#define BB 16
#define CC 1024
#define TT 2048
#define NN 1024
#define OCHUNKS 16
#define OPER    (CC / OCHUNKS)   // 64

#define SEG    8
#define SEGLEN (TT / SEG)        // 256
#define WARM   128
#define TC     32

__device__ float g_sx[BB * TT];             // 128 KB
__device__ float g_cs_part[OCHUNKS * NN];   // 64 KB

// ---------------------------------------------------------------------------
// Kernel 1: fused rowsum (blocks 0..127) + weight colsum partials (128..191).
// Rowsum arithmetic identical to round-1 (single acc, sequential c).
// ---------------------------------------------------------------------------
__global__ void reduce_fused_kernel(const float* __restrict__ x,
                                    const float* __restrict__ w) {
    if (blockIdx.x < 128) {
        // rowsum: sx[b,t] = sum_c x[b,c,t]
        const int idx = blockIdx.x * 256 + threadIdx.x;   // b*TT + t
        const int b = idx / TT;
        const int t = idx % TT;
        const float* p = x + (size_t)b * CC * TT + t;
        float acc = 0.0f;
#pragma unroll 32
        for (int c = 0; c < CC; ++c) {
            acc = __fadd_rn(acc, __ldcs(p + (size_t)c * TT));
        }
        g_sx[idx] = acc;
    } else {
        // colsum partials: chunk oc, 64 sequential rows
        const int bid = blockIdx.x - 128;                 // 0..63
        const int oc   = bid >> 2;                        // 0..15
        const int n    = (bid & 3) * 256 + threadIdx.x;   // 0..1023
        const float* p = w + (size_t)oc * OPER * NN + n;
        float acc = 0.0f;
#pragma unroll 16
        for (int o = 0; o < OPER; ++o) {
            acc = __fadd_rn(acc, p[(size_t)o * NN]);
        }
        g_cs_part[oc * NN + n] = acc;
    }
}

// ---------------------------------------------------------------------------
// Kernel 2: segmented LIF + coalesced spike writes.
// grid (NN/64, BB, SEG) = 2048 blocks, block 64 (thread = one n).
// cs[n] reduced inline from partials (same sequential oc order as before).
// Per 32-step chunk: spikes into SMEM rotate-swizzled, then 128B row writes.
// ---------------------------------------------------------------------------
__global__ void lif_seg_kernel(const float* __restrict__ v0,
                               float* __restrict__ out) {
    const int tid = threadIdx.x;               // 0..63
    const int n0  = blockIdx.x * 64;
    const int b   = blockIdx.y;
    const int s   = blockIdx.z;
    const int n   = n0 + tid;

    __shared__ float sxs[WARM + SEGLEN];       // 384 floats
    __shared__ float buf[TC * 64];             // 8 KB

    // cs[n] = sum over 16 partials, sequential (identical rounding to r1)
    float csn = 0.0f;
#pragma unroll
    for (int oc = 0; oc < OCHUNKS; ++oc) {
        csn = __fadd_rn(csn, g_cs_part[oc * NN + n]);
    }

    const int tseg = s * SEGLEN;
    const float* sxb = g_sx + b * TT;

    // stage sx[tseg-WARM .. tseg+SEGLEN) ; skip invalid prefix for s=0
    for (int i = tid; i < WARM + SEGLEN; i += 64) {
        int g = tseg - WARM + i;
        if (g >= 0) sxs[i] = sxb[g];
    }
    __syncthreads();

    float v = (s == 0) ? v0[n] : 0.0f;

    // warm-up (no writes): converges to exact state via hard resets
    if (s != 0) {
#pragma unroll 8
        for (int k = 0; k < WARM; ++k) {
            float cur = __fmul_rn(sxs[k], csn);
            v = __fadd_rn(v, __fmul_rn(__fsub_rn(cur, v), 0.1f));
            if (v >= 1.0f) v = 0.0f;
        }
    }

    float* outb = out + ((size_t)b * NN + n0) * TT + tseg;
    const int w    = tid >> 5;
    const int lane = tid & 31;

    for (int c8 = 0; c8 < SEGLEN; c8 += TC) {
#pragma unroll
        for (int k = 0; k < TC; ++k) {
            float cur = __fmul_rn(sxs[WARM + c8 + k], csn);
            v = __fadd_rn(v, __fmul_rn(__fsub_rn(cur, v), 0.1f));
            float sp;
            if (v >= 1.0f) { sp = 1.0f; v = 0.0f; } else { sp = 0.0f; }
            buf[k * 64 + ((tid + k) & 63)] = sp;
        }
        __syncthreads();

        // transposed, coalesced write-out (conflict-free via rotate swizzle)
        for (int r = w; r < 64; r += 2) {
            outb[(size_t)r * TT + c8 + lane] = buf[lane * 64 + ((r + lane) & 63)];
        }
        __syncthreads();
    }
}

// ---------------------------------------------------------------------------
extern "C" void kernel_launch(void* const* d_in, const int* in_sizes, int n_in,
                              void* d_out, int out_size) {
    const float* x  = (const float*)d_in[0];
    const float* wt = (const float*)d_in[1];
    const float* v0 = (const float*)d_in[2];
    float* out = (float*)d_out;

    (void)in_sizes; (void)n_in; (void)out_size;

    reduce_fused_kernel<<<192, 256>>>(x, wt);
    lif_seg_kernel<<<dim3(NN / 64, BB, SEG), 64>>>(v0, out);
}

// round 3
// speedup vs baseline: 2.4571x; 1.2094x over previous
#include <cuda_runtime.h>
#include <cstddef>

// SNNLayer: x(16,1024,2048) fp32, weight(1024,1024) fp32, v0(1024) fp32
// einsum('bct,on->bnt') factorizes: inp[b,n,t] = sx[b,t] * cs[n]
//   sx[b,t] = sum_c x[b,c,t]   (sequential-c order, bit-identical to r1/r2)
//   cs[n]   = sum_o w[o,n]     (16 chunks of 64, sequential, as r1/r2)
// LIF: v += (i - v)*0.1 ; spike = v>=1 ; hard reset to exact 0.
// Parallel-in-T: 8 segments x 256 steps, warm-up 64 steps from v=0
// (hard reset makes replica bit-exact after first common fire).

#define BB 16
#define CC 1024
#define TT 2048
#define NN 1024
#define OCHUNKS 16
#define OPER    (CC / OCHUNKS)   // 64

#define SEG    8
#define SEGLEN (TT / SEG)        // 256
#define WARM   64
#define TC     32

__device__ float g_sx[BB * TT];             // 128 KB
__device__ float g_cs_part[OCHUNKS * NN];   // 64 KB

// ---------------------------------------------------------------------------
// Kernel 1: fused rowsum (blocks 0..127) + weight colsum partials (128..191).
// Rowsum arithmetic identical to previous rounds (single acc, sequential c).
// unroll 64 -> 64 independent LDGs batched per thread (MLP to cover DRAM lat).
// ---------------------------------------------------------------------------
__global__ void __launch_bounds__(256)
reduce_fused_kernel(const float* __restrict__ x, const float* __restrict__ w) {
    if (blockIdx.x < 128) {
        const int idx = blockIdx.x * 256 + threadIdx.x;   // b*TT + t
        const int b = idx / TT;
        const int t = idx % TT;
        const float* p = x + (size_t)b * CC * TT + t;
        float acc = 0.0f;
#pragma unroll 64
        for (int c = 0; c < CC; ++c) {
            acc = __fadd_rn(acc, __ldcs(p + (size_t)c * TT));
        }
        g_sx[idx] = acc;
    } else {
        const int bid = blockIdx.x - 128;                 // 0..63
        const int oc  = bid >> 2;                         // 0..15
        const int n   = (bid & 3) * 256 + threadIdx.x;    // 0..1023
        const float* p = w + (size_t)oc * OPER * NN + n;
        float acc = 0.0f;
#pragma unroll 16
        for (int o = 0; o < OPER; ++o) {
            acc = __fadd_rn(acc, p[(size_t)o * NN]);
        }
        g_cs_part[oc * NN + n] = acc;
    }
}

// ---------------------------------------------------------------------------
// Kernel 2: segmented LIF, spikes bit-packed in registers, shuffle transpose,
// STG.128 coalesced writes. No per-chunk barriers, no per-step shared stores.
// grid (NN/128, BB, SEG) = 1024 blocks, block 128 (thread = one n).
// ---------------------------------------------------------------------------
__global__ void __launch_bounds__(128)
lif_seg_kernel(const float* __restrict__ v0, float* __restrict__ out) {
    const int tid = threadIdx.x;               // 0..127
    const int n0  = blockIdx.x * 128;
    const int b   = blockIdx.y;
    const int s   = blockIdx.z;
    const int n   = n0 + tid;

    __shared__ float sxs[WARM + SEGLEN];       // 320 floats

    // cs[n] = sum over 16 partials, sequential (identical rounding)
    float csn = 0.0f;
#pragma unroll
    for (int oc = 0; oc < OCHUNKS; ++oc) {
        csn = __fadd_rn(csn, g_cs_part[oc * NN + n]);
    }

    const int tseg = s * SEGLEN;
    const float* sxb = g_sx + b * TT;

    for (int i = tid; i < WARM + SEGLEN; i += 128) {
        int g = tseg - WARM + i;
        if (g >= 0) sxs[i] = sxb[g];
    }
    __syncthreads();

    float v = (s == 0) ? v0[n] : 0.0f;

    if (s != 0) {
#pragma unroll 16
        for (int k = 0; k < WARM; ++k) {
            float cur = __fmul_rn(sxs[k], csn);
            v = __fadd_rn(v, __fmul_rn(__fsub_rn(cur, v), 0.1f));
            if (v >= 1.0f) v = 0.0f;
        }
    }

    const int lane = tid & 31;
    const int w    = tid >> 5;
    const int src  = lane >> 3;                // 0..3: row-within-group
    const int j0   = (lane & 7) << 2;          // 0,4,...,28: t offset
    float* outb = out + ((size_t)b * NN + n0) * TT + tseg;

    for (int c8 = 0; c8 < SEGLEN; c8 += TC) {
        unsigned u = 0u;
#pragma unroll
        for (int k = 0; k < TC; ++k) {
            float cur = __fmul_rn(sxs[WARM + c8 + k], csn);
            v = __fadd_rn(v, __fmul_rn(__fsub_rn(cur, v), 0.1f));
            if (v >= 1.0f) { u |= (1u << k); v = 0.0f; }
        }

        // Transpose within warp via shuffle; 8 STG.128 per warp per chunk.
        // Iteration rr covers rows rr*4 .. rr*4+3 of this warp's 32 neurons.
#pragma unroll
        for (int rr = 0; rr < 8; ++rr) {
            const int rloc = (rr << 2) + src;                  // 0..31
            const unsigned word = __shfl_sync(0xffffffffu, u, rloc);
            float4 f;
            f.x = (word >> (j0 + 0)) & 1u ? 1.0f : 0.0f;
            f.y = (word >> (j0 + 1)) & 1u ? 1.0f : 0.0f;
            f.z = (word >> (j0 + 2)) & 1u ? 1.0f : 0.0f;
            f.w = (word >> (j0 + 3)) & 1u ? 1.0f : 0.0f;
            const int row = (w << 5) + rloc;                   // 0..127
            *reinterpret_cast<float4*>(outb + (size_t)row * TT + c8 + j0) = f;
        }
    }
}

// ---------------------------------------------------------------------------
extern "C" void kernel_launch(void* const* d_in, const int* in_sizes, int n_in,
                              void* d_out, int out_size) {
    const float* x  = (const float*)d_in[0];
    const float* wt = (const float*)d_in[1];
    const float* v0 = (const float*)d_in[2];
    float* out = (float*)d_out;

    (void)in_sizes; (void)n_in; (void)out_size;

    reduce_fused_kernel<<<192, 256>>>(x, wt);
    lif_seg_kernel<<<dim3(NN / 128, BB, SEG), 128>>>(v0, out);
}